// round 5
// baseline (speedup 1.0000x reference)
#include <cuda_runtime.h>

#define BATCH 128
#define NSTEP 16
#define DMC 0.95122942450071400910f   // exp(-1/20)
#define DSC 0.81873075307798185867f   // exp(-1/5)

#define N_IN 784
#define N_L1 25088     // 32x28x28
#define N_P1 6272      // 32x14x14
#define N_L2 12544     // 64x14x14
#define N_P2 3136      // 64x7x7
#define N_F1 600

// ------------------------- persistent state ---------------------------------
__device__ float g_input_u[BATCH*N_IN];

__device__ float g_um1[BATCH*N_L1], g_us1[BATCH*N_L1];
__device__ unsigned char g_sav1[BATCH*N_L1], g_te1[BATCH*N_L1], g_lat1[BATCH*N_L1];
__device__ float g_p1[BATCH*N_P1];

__device__ float g_um2[BATCH*N_L2], g_us2[BATCH*N_L2];
__device__ unsigned char g_sav2[BATCH*N_L2], g_te2[BATCH*N_L2], g_lat2[BATCH*N_L2];
__device__ float g_p2[BATCH*N_P2];

__device__ float g_umf1[BATCH*N_F1], g_usf1[BATCH*N_F1];
__device__ unsigned char g_savf1[BATCH*N_F1];

__device__ float g_umf2[BATCH*10], g_usf2[BATCH*10];
__device__ unsigned char g_savf2[BATCH*10];
__device__ float g_tel[BATCH*10], g_outt[BATCH*10], g_outu[BATCH*10];

__device__ unsigned long long g_counts[5];
__device__ float g_wt1[3136*600];     // transposed w_fc1: [i][j]

// ------------------------------ init ----------------------------------------
__global__ void k_init() {
    int n = BATCH * N_L1;
    for (int i = blockIdx.x * blockDim.x + threadIdx.x; i < n;
         i += gridDim.x * blockDim.x) {
        g_um1[i] = 0.f; g_us1[i] = 0.f;
        g_sav1[i] = 1; g_te1[i] = 0; g_lat1[i] = 16;
        if (i < BATCH * N_L2) {
            g_um2[i] = 0.f; g_us2[i] = 0.f;
            g_sav2[i] = 1; g_te2[i] = 0; g_lat2[i] = 16;
        }
        if (i < BATCH * N_F1) { g_umf1[i] = 0.f; g_usf1[i] = 0.f; g_savf1[i] = 1; }
        if (i < BATCH * 10) {
            g_umf2[i] = 0.f; g_usf2[i] = 0.f; g_savf2[i] = 1;
            g_tel[i] = 0.f;
            g_outt[i] = 16.f;     // !!! reference inits out_t = NUM_STEPS * ones
            g_outu[i] = 0.f;
        }
        if (i < BATCH * N_IN) g_input_u[i] = 0.f;
        if (i < 5) g_counts[i] = 0ull;
    }
}

__global__ void k_transpose(const float* __restrict__ w) {
    int n = 3136 * 600;
    for (int m = blockIdx.x * blockDim.x + threadIdx.x; m < n;
         m += gridDim.x * blockDim.x) {
        int j = m / 3136, i = m % 3136;
        g_wt1[i * 600 + j] = w[m];
    }
}

// --------------- K1: input encode + conv1 + L1 + pool1 -----------------------
#define K1_SMEM (4096 + 3200 + 25088 + 25088)
__global__ void __launch_bounds__(256) k1(const float* __restrict__ input,
                                          const float* __restrict__ w1) {
    extern __shared__ char sm1[];
    float* s_in = (float*)sm1;                              // 1024 floats
    float* s_w  = (float*)(sm1 + 4096);                     // 800 floats
    unsigned char* s_spk = (unsigned char*)(sm1 + 7296);    // 25088
    unsigned char* s_lat = (unsigned char*)(sm1 + 7296 + 25088);
    __shared__ int s_c0, s_c1;

    int b = blockIdx.x, t = threadIdx.x;
    if (t == 0) { s_c0 = 0; s_c1 = 0; }
    for (int i = t; i < 1024; i += 256) s_in[i] = 0.f;
    for (int i = t; i < 800;  i += 256) s_w[i] = w1[i];
    __syncthreads();

    // input encoding neuron
    int lc0 = 0;
    for (int i = t; i < N_IN; i += 256) {
        float u = g_input_u[b * N_IN + i];
        float notspk = (u > 1.f) ? 0.f : 1.f;    // 1 - previous spike
        u = u * DMC * notspk + input[b * N_IN + i] * 0.3f;
        g_input_u[b * N_IN + i] = u;
        float spk = (u > 1.f) ? 1.f : 0.f;
        s_in[((i / 28) + 2) * 32 + (i % 28) + 2] = spk;
        lc0 += (spk > 0.f);
    }
    atomicAdd(&s_c0, lc0);
    __syncthreads();

    // conv1 (row-register tiling) + L1 neuron update
    int lc1 = 0;
    for (int task = t; task < 896; task += 256) {   // 32 ch * 28 rows
        int o = task / 28, y = task % 28;
        const float* wp = s_w + o * 25;
        float acc[28];
        #pragma unroll
        for (int i = 0; i < 28; i++) acc[i] = 0.f;
        #pragma unroll
        for (int ky = 0; ky < 5; ky++) {
            const float* row = s_in + (y + ky) * 32;
            float r[32];
            #pragma unroll
            for (int i = 0; i < 32; i++) r[i] = row[i];
            #pragma unroll
            for (int kx = 0; kx < 5; kx++) {
                float wv = wp[ky * 5 + kx];
                #pragma unroll
                for (int xi = 0; xi < 28; xi++) acc[xi] += wv * r[xi + kx];
            }
        }
        int base = o * 784 + y * 28;
        #pragma unroll 4
        for (int xi = 0; xi < 28; xi++) {
            int idx = base + xi;
            int g = b * N_L1 + idx;
            float um = g_um1[g] * DMC + acc[xi];
            float us = g_us1[g] * DSC + acc[xi];
            g_um1[g] = um; g_us1[g] = us;
            int sav = g_sav1[g], te = g_te1[g], lat = g_lat1[g];
            float u = sav ? (um - us) : 0.f;
            int spk = (u - 1.f > 0.f) ? 1 : 0;
            if (te > 0 || um != 0.f) te++;
            if (spk) { sav = 0; lat = te + 1; }
            g_sav1[g] = (unsigned char)sav;
            g_te1[g]  = (unsigned char)te;
            g_lat1[g] = (unsigned char)lat;
            s_spk[idx] = (unsigned char)spk;
            s_lat[idx] = (unsigned char)lat;
            lc1 += spk;
        }
    }
    atomicAdd(&s_c1, lc1);
    __syncthreads();
    if (t == 0) {
        atomicAdd(&g_counts[0], (unsigned long long)s_c0);
        atomicAdd(&g_counts[1], (unsigned long long)s_c1);
    }

    // latency min-pool 2x2 -> float 0/1
    for (int L = t; L < N_P1; L += 256) {
        int ci = L / 196, p = L % 196, y = p / 14, x = p % 14;
        int base = ci * 784 + 2 * y * 28 + 2 * x;
        int la = s_lat[base],       lb = s_lat[base + 1];
        int lcv = s_lat[base + 28], ld = s_lat[base + 29];
        int lmin = min(min(la, lb), min(lcv, ld));
        int bit = (s_spk[base] && la == lmin) || (s_spk[base + 1] && lb == lmin) ||
                  (s_spk[base + 28] && lcv == lmin) || (s_spk[base + 29] && ld == lmin);
        g_p1[b * N_P1 + L] = bit ? 1.f : 0.f;
    }
}

// ------------- K2: sparse-scatter conv2 + L2 + pool2 -------------------------
#define K2_SMEM (50176 + 12544 + 12544 + 12544)
__global__ void __launch_bounds__(256) k2(const float* __restrict__ w2) {
    extern __shared__ char sm2[];
    float* s_acc = (float*)sm2;                                   // 12544 floats
    unsigned short* s_list = (unsigned short*)(sm2 + 50176);      // <=6272
    unsigned char* s_spk = (unsigned char*)(sm2 + 62720);         // 12544
    unsigned char* s_lat = (unsigned char*)(sm2 + 75264);         // 12544
    __shared__ int s_n, s_cnt;

    int b = blockIdx.x, t = threadIdx.x;
    if (t == 0) s_cnt = 0;
    for (int i = t; i < N_L2; i += 256) s_acc[i] = 0.f;

    // deterministic active-input list (warp 0, ballot compaction)
    if (t < 32) {
        int n = 0;
        for (int base = 0; base < N_P1; base += 32) {
            float v = g_p1[b * N_P1 + base + t];
            unsigned m = __ballot_sync(0xffffffffu, v != 0.f);
            if (v != 0.f) s_list[n + __popc(m & ((1u << t) - 1u))] =
                              (unsigned short)(base + t);
            n += __popc(m);
        }
        if (t == 0) s_n = n;
    }
    __syncthreads();

    // scatter: thread owns (o = t/4, output rows rr ≡ t%4 mod 4) — race-free.
    // out[o][rr][ox] += w2[o][ci][ky][kx] with ky = y-rr+2, ox = x+2-kx
    int n = s_n;
    int o = t >> 2, part = t & 3;
    for (int q = 0; q < n; q++) {
        int e = s_list[q];
        int ci = e / 196, p = e % 196, y = p / 14, x = p % 14;
        const float* wb = w2 + (o * 32 + ci) * 25;
        for (int rr = part; rr < 14; rr += 4) {
            int ky = y - rr + 2;
            if (ky < 0 || ky > 4) continue;
            float* arow = s_acc + o * 196 + rr * 14;
            const float* wr = wb + ky * 5;
            #pragma unroll
            for (int kx = 0; kx < 5; kx++) {
                int ox = x + 2 - kx;
                if (ox >= 0 && ox < 14) arow[ox] += wr[kx];
            }
        }
    }
    __syncthreads();

    // L2 neuron update
    int lc = 0;
    for (int idx = t; idx < N_L2; idx += 256) {
        int g = b * N_L2 + idx;
        float acc = s_acc[idx];
        float um = g_um2[g] * DMC + acc;
        float us = g_us2[g] * DSC + acc;
        g_um2[g] = um; g_us2[g] = us;
        int sav = g_sav2[g], te = g_te2[g], lat = g_lat2[g];
        float u = sav ? (um - us) : 0.f;
        int spk = (u - 1.f > 0.f) ? 1 : 0;
        if (te > 0 || um != 0.f) te++;
        if (spk) { sav = 0; lat = te + 1; }
        g_sav2[g] = (unsigned char)sav;
        g_te2[g]  = (unsigned char)te;
        g_lat2[g] = (unsigned char)lat;
        s_spk[idx] = (unsigned char)spk;
        s_lat[idx] = (unsigned char)lat;
        lc += spk;
    }
    atomicAdd(&s_cnt, lc);
    __syncthreads();
    if (t == 0) atomicAdd(&g_counts[2], (unsigned long long)s_cnt);

    // pool2 -> float 0/1
    for (int L = t; L < N_P2; L += 256) {
        int ci = L / 49, p = L % 49, y = p / 7, x = p % 7;
        int base = ci * 196 + 2 * y * 14 + 2 * x;
        int la = s_lat[base],       lb = s_lat[base + 1];
        int lcv = s_lat[base + 14], ld = s_lat[base + 15];
        int lmin = min(min(la, lb), min(lcv, ld));
        int bit = (s_spk[base] && la == lmin) || (s_spk[base + 1] && lb == lmin) ||
                  (s_spk[base + 14] && lcv == lmin) || (s_spk[base + 15] && ld == lmin);
        g_p2[b * N_P2 + L] = bit ? 1.f : 0.f;
    }
}

// --------------- K34: sparse fc1 + F1 + fc2 + output -------------------------
__global__ void __launch_bounds__(320) k34(const float* __restrict__ wf2) {
    __shared__ unsigned short s_list[N_P2];
    __shared__ unsigned char s_f1[600];
    __shared__ int s_n, s_c3, s_c4;
    int b = blockIdx.x, t = threadIdx.x;
    if (t == 0) { s_c3 = 0; s_c4 = 0; }

    if (t < 32) {
        int n = 0;
        for (int base = 0; base < N_P2; base += 32) {
            float v = g_p2[b * N_P2 + base + t];
            unsigned m = __ballot_sync(0xffffffffu, v != 0.f);
            if (v != 0.f) s_list[n + __popc(m & ((1u << t) - 1u))] =
                              (unsigned short)(base + t);
            n += __popc(m);
        }
        if (t == 0) s_n = n;
    }
    __syncthreads();

    // fc1: sum transposed-weight rows for active inputs (fixed ascending order)
    int n = s_n;
    float a0 = 0.f, a1 = 0.f;
    bool h2 = (t + 320) < 600;
    for (int q = 0; q < n; q++) {
        const float* row = g_wt1 + (int)s_list[q] * 600;
        a0 += row[t];
        if (h2) a1 += row[t + 320];
    }

    int lc = 0;
    #pragma unroll
    for (int rep = 0; rep < 2; rep++) {
        int j = t + rep * 320;
        if (j >= 600) break;
        float acc = rep ? a1 : a0;
        int g = b * N_F1 + j;
        float um = g_umf1[g] * DMC + acc;
        float us = g_usf1[g] * DSC + acc;
        g_umf1[g] = um; g_usf1[g] = us;
        int sav = g_savf1[g];
        float u = sav ? (um - us) : 0.f;
        int spk = (u - 1.f > 0.f) ? 1 : 0;
        if (spk) { g_savf1[g] = 0; lc++; }
        s_f1[j] = (unsigned char)spk;
    }
    atomicAdd(&s_c3, lc);
    __syncthreads();

    // fc2: warp j handles output neuron j
    int j = t >> 5, lane = t & 31;
    float acc = 0.f;
    for (int i = lane; i < 600; i += 32)
        if (s_f1[i]) acc += wf2[j * 600 + i];
    #pragma unroll
    for (int off = 16; off; off >>= 1)
        acc += __shfl_xor_sync(0xffffffffu, acc, off);

    if (lane == 0) {
        int g = b * 10 + j;
        float um = g_umf2[g] * DMC + acc;
        float us = g_usf2[g] * DSC + acc;
        g_umf2[g] = um; g_usf2[g] = us;
        int sav = g_savf2[g];
        float u = sav ? (um - us) : 0.f;
        int spk = (u - 1.f > 0.f) ? 1 : 0;
        if (spk) g_savf2[g] = 0;
        float tel = g_tel[g];
        float uflag = (u != 0.f) ? 1.f : 0.f;
        if (tel + uflag != 0.f) tel += 1.f;
        g_tel[g] = tel;
        if (spk) {
            g_outt[g] += (tel - 16.f);
            g_outu[g] += u;
            atomicAdd(&s_c4, 1);
        }
    }
    __syncthreads();
    if (t == 0) {
        atomicAdd(&g_counts[3], (unsigned long long)s_c3);
        atomicAdd(&g_counts[4], (unsigned long long)s_c4);
    }
}

// ------------------- K5: pack outputs ---------------------------------------
__global__ void k5(float* __restrict__ out) {
    int i = blockIdx.x * blockDim.x + threadIdx.x;
    if (i < 1280) out[i] = g_outt[i];
    else if (i < 2560) out[i] = g_outu[i - 1280];
    else if (i < 2565) out[i] = (float)g_counts[i - 2560];
}

// ------------------------------ launch --------------------------------------
extern "C" void kernel_launch(void* const* d_in, const int* in_sizes, int n_in,
                              void* d_out, int out_size) {
    // Robust binding: match by element count OR byte count (no collisions).
    const float *input = 0, *w1 = 0, *w2 = 0, *wf1 = 0, *wf2 = 0;
    for (int i = 0; i < n_in; i++) {
        long s = in_sizes[i];
        if (s == 100352 || s == 401408)        input = (const float*)d_in[i];
        else if (s == 800 || s == 3200)        w1    = (const float*)d_in[i];
        else if (s == 51200 || s == 204800)    w2    = (const float*)d_in[i];
        else if (s == 1881600 || s == 7526400) wf1   = (const float*)d_in[i];
        else if (s == 6000 || s == 24000)      wf2   = (const float*)d_in[i];
    }
    if (!input || !w1 || !w2 || !wf1 || !wf2) {
        const float* p[5] = {0, 0, 0, 0, 0};
        int k = 0;
        for (int i = 0; i < n_in && k < 5; i++)
            if (in_sizes[i] > 8) p[k++] = (const float*)d_in[i];
        if (k < 5)
            for (int i = 0; i < n_in && k < 5; i++) p[k++] = (const float*)d_in[i];
        input = p[0]; w1 = p[1]; w2 = p[2]; wf1 = p[3]; wf2 = p[4];
    }
    float* out = (float*)d_out;

    cudaFuncSetAttribute(k1, cudaFuncAttributeMaxDynamicSharedMemorySize, K1_SMEM);
    cudaFuncSetAttribute(k2, cudaFuncAttributeMaxDynamicSharedMemorySize, K2_SMEM);

    k_init<<<512, 256>>>();
    k_transpose<<<512, 256>>>(wf1);
    for (int s = 0; s < NSTEP; s++) {
        k1<<<BATCH, 256, K1_SMEM>>>(input, w1);
        k2<<<BATCH, 256, K2_SMEM>>>(w2);
        k34<<<BATCH, 320>>>(wf2);
    }
    k5<<<11, 256>>>(out);
}

// round 6
// speedup vs baseline: 3.7373x; 3.7373x over previous
#include <cuda_runtime.h>

#define BATCH 128
#define NSTEP 16
#define DMC 0.95122942450071400910f   // exp(-1/20)
#define DSC 0.81873075307798185867f   // exp(-1/5)
#define NT 896

__device__ float g_um1[BATCH*25088], g_us1[BATCH*25088];
__device__ float g_um2[BATCH*12544], g_us2[BATCH*12544];
__device__ float g_wt1[3136*600];                 // transposed w_fc1 [i][j]
__device__ unsigned long long g_bc[BATCH*8];      // per-block spike counts

// ---------------- shared memory layout (bytes) ----------------
#define O_W1     0        // 800 f                -> 3200
#define O_TE1    3200     // 25088 u8             -> 28288
#define O_LAT1   28288    // 25088 u8             -> 53376  (b0-4 lat, b6 dead, b7 spk)
#define O_TE2    53376    // 12544 u8             -> 65920
#define O_LAT2   65920    // 12544 u8             -> 78464
#define O_RF1    78464    // 896 u8 rowflags      -> 79360  (b0 everActive, b1 allDead)
#define O_RF2    79360    // 896 u8               -> 80256
#define O_UMF1   80256    // 600 f                -> 82656
#define O_USF1   82656    // 600 f                -> 85056
#define O_SAVF1  85056    // 600 u8               -> 85656
#define O_UMF2   85656    // 10 f                 -> 85696
#define O_USF2   85696    // 10 f                 -> 85736
#define O_TEL    85736    // 10 f                 -> 85776
#define O_OUTT   85776    // 10 f                 -> 85816
#define O_OUTU   85816    // 10 f                 -> 85856
#define O_SAVF2  85856    // 10 u8                -> 85872 (pad)
#define O_ENCU   85872    // 784 f                -> 89008
#define O_ENCSPK 89008    // 784 u8               -> 89792
#define O_ENCN   89792    // 28 i32               -> 89904
#define O_ENCB   89904    // 28*28 u8             -> 90688
#define O_B1N    90688    // 14 i32               -> 90752 (pad)
#define O_B1     90752    // 14*448 u16           -> 103296
#define O_PM     103296   // 98 u32               -> 103688
#define O_F1S    103688   // 600 u8               -> 104304 (pad)
#define O_CNT    104304   // 8 i32                -> 104448 (pad)
#define O_BIG    104448   // 28672 f (acc1) / 16128 f (acc2 alias) -> 219136
#define SMEM_TOTAL 219136

__global__ void k_transpose(const float* __restrict__ w) {
    int n = 3136 * 600;
    for (int m = blockIdx.x * blockDim.x + threadIdx.x; m < n;
         m += gridDim.x * blockDim.x) {
        int j = m / 3136, i = m % 3136;
        g_wt1[i * 600 + j] = w[m];
    }
}

__global__ void __launch_bounds__(NT, 1) k_fused(
    const float* __restrict__ input, const float* __restrict__ w1g,
    const float* __restrict__ w2, const float* __restrict__ wf2,
    float* __restrict__ out)
{
    extern __shared__ char sm[];
    float*          s_w1    = (float*)(sm + O_W1);
    unsigned char*  s_te1   = (unsigned char*)(sm + O_TE1);
    unsigned char*  s_lat1  = (unsigned char*)(sm + O_LAT1);
    unsigned char*  s_te2   = (unsigned char*)(sm + O_TE2);
    unsigned char*  s_lat2  = (unsigned char*)(sm + O_LAT2);
    unsigned char*  s_rf1   = (unsigned char*)(sm + O_RF1);
    unsigned char*  s_rf2   = (unsigned char*)(sm + O_RF2);
    float*          s_umf1  = (float*)(sm + O_UMF1);
    float*          s_usf1  = (float*)(sm + O_USF1);
    unsigned char*  s_savf1 = (unsigned char*)(sm + O_SAVF1);
    float*          s_umf2  = (float*)(sm + O_UMF2);
    float*          s_usf2  = (float*)(sm + O_USF2);
    float*          s_tel   = (float*)(sm + O_TEL);
    float*          s_outt  = (float*)(sm + O_OUTT);
    float*          s_outu  = (float*)(sm + O_OUTU);
    unsigned char*  s_savf2 = (unsigned char*)(sm + O_SAVF2);
    float*          s_encu  = (float*)(sm + O_ENCU);
    unsigned char*  s_encspk= (unsigned char*)(sm + O_ENCSPK);
    int*            s_encn  = (int*)(sm + O_ENCN);
    unsigned char*  s_encb  = (unsigned char*)(sm + O_ENCB);
    int*            s_b1n   = (int*)(sm + O_B1N);
    unsigned short* s_b1    = (unsigned short*)(sm + O_B1);
    unsigned*       s_pm    = (unsigned*)(sm + O_PM);
    unsigned char*  s_f1s   = (unsigned char*)(sm + O_F1S);
    int*            s_cnt   = (int*)(sm + O_CNT);
    float*          s_big   = (float*)(sm + O_BIG);

    int b = blockIdx.x, t = threadIdx.x;
    int w = t >> 5, lane = t & 31;
    int o1 = t / 28, rr1 = t % 28;    // conv1/L1 row owner (32x28)
    int o2 = t / 14, rr2 = t % 14;    // conv2/L2 row owner (64x14)

    // ------------------------------ init ------------------------------------
    for (int i = t; i < 25088; i += NT) { s_te1[i] = 0; s_lat1[i] = 16; }
    for (int i = t; i < 12544; i += NT) { s_te2[i] = 0; s_lat2[i] = 16; }
    s_rf1[t] = 0; s_rf2[t] = 0;
    if (t < 600) { s_umf1[t] = 0.f; s_usf1[t] = 0.f; s_savf1[t] = 1; }
    if (t < 784) s_encu[t] = 0.f;
    if (t < 800) s_w1[t] = w1g[t];
    if (t < 10) { s_umf2[t] = 0.f; s_usf2[t] = 0.f; s_tel[t] = 0.f;
                  s_outt[t] = 16.f; s_outu[t] = 0.f; s_savf2[t] = 1; }
    if (t < 8) s_cnt[t] = 0;
    __syncthreads();

    int c0 = 0, c1 = 0, c2 = 0, c3 = 0, c4 = 0;

    for (int s = 0; s < NSTEP; s++) {
        // ---- P1: input encode + zero conv1 accumulator ----
        if (t < 784) {
            float u = s_encu[t];
            float notspk = (u > 1.f) ? 0.f : 1.f;
            u = u * DMC * notspk + input[b * 784 + t] * 0.3f;
            s_encu[t] = u;
            int spk = (u > 1.f) ? 1 : 0;
            s_encspk[t] = (unsigned char)spk;
            c0 += spk;
        }
        for (int k = t; k < 28672; k += NT) s_big[k] = 0.f;
        __syncthreads();

        // ---- P2: input-spike row buckets (warp w = input row w) ----
        {
            int v = (lane < 28) ? s_encspk[w * 28 + lane] : 0;
            unsigned m = __ballot_sync(0xffffffffu, v != 0);
            if (v) s_encb[w * 28 + __popc(m & ((1u << lane) - 1u))] = (unsigned char)lane;
            if (lane == 0) s_encn[w] = __popc(m);
        }
        __syncthreads();

        // ---- P3: conv1 sparse scatter into own padded row (width 32) ----
        bool touched1 = false;
        {
            float* row = s_big + t * 32;
            #pragma unroll
            for (int dy = -2; dy <= 2; dy++) {
                int y = rr1 + dy;
                if ((unsigned)y >= 28u) continue;
                int nb = s_encn[y];
                if (!nb) continue;
                touched1 = true;
                const float* wr = s_w1 + o1 * 25 + (dy + 2) * 5;
                float wa = wr[0], wbv = wr[1], wc = wr[2], wd = wr[3], we = wr[4];
                const unsigned char* bk = s_encb + y * 28;
                for (int q = 0; q < nb; q++) {
                    float* rp = row + bk[q];   // out col ox at row[ox+2]; idx = x+4-kx
                    rp[4] += wa; rp[3] += wbv; rp[2] += wc; rp[1] += wd; rp[0] += we;
                }
            }
        }
        // ---- P4: L1 neuron update (own row only: no sync needed after P3) ----
        {
            unsigned char rf = s_rf1[t];
            int idx = t * 28;
            if (rf & 2) {
                for (int c = 0; c < 28; c++) s_lat1[idx + c] &= 0x7F;
            } else if ((rf & 1) || touched1) {
                bool wasActive = rf & 1;
                float* row = s_big + t * 32;
                bool alldead = true;
                int gbase = b * 25088 + idx;
                for (int ch = 0; ch < 28; ch += 4) {
                    float4 um4, us4;
                    if (wasActive) {
                        um4 = *(const float4*)(g_um1 + gbase + ch);
                        us4 = *(const float4*)(g_us1 + gbase + ch);
                    } else { um4 = make_float4(0.f,0.f,0.f,0.f); us4 = um4; }
                    float* um = &um4.x; float* us = &us4.x;
                    #pragma unroll
                    for (int j = 0; j < 4; j++) {
                        int c = ch + j;
                        float acc = row[c + 2];
                        float umv = um[j] * DMC + acc;
                        float usv = us[j] * DSC + acc;
                        um[j] = umv; us[j] = usv;
                        unsigned char tb = s_te1[idx + c];
                        unsigned char lb = s_lat1[idx + c];
                        bool sav = !(lb & 0x40);
                        float u = sav ? (umv - usv) : 0.f;
                        int spk = (u - 1.f > 0.f) ? 1 : 0;
                        if (tb > 0 || umv != 0.f) tb++;
                        unsigned char nlb = spk ? (unsigned char)((tb + 1) | 0xC0)
                                               : (unsigned char)(lb & 0x5F);
                        s_te1[idx + c] = tb; s_lat1[idx + c] = nlb;
                        alldead = alldead && ((nlb & 0x40) != 0);
                        c1 += spk;
                    }
                    *(float4*)(g_um1 + gbase + ch) = um4;
                    *(float4*)(g_us1 + gbase + ch) = us4;
                }
                rf |= 1; if (alldead) rf |= 2;
                s_rf1[t] = rf;
            }
        }
        __syncthreads();

        // ---- P5: zero conv2 accumulator + pool1 -> row buckets ----
        for (int k = t; k < 16128; k += NT) s_big[k] = 0.f;
        if (w < 14) {
            int py = w, n = 0;
            for (int ci = 0; ci < 32; ci++) {
                int bit = 0;
                if (lane < 14) {
                    int base = ci * 784 + (2 * py) * 28 + 2 * lane;
                    unsigned a = s_lat1[base],      b2 = s_lat1[base + 1];
                    unsigned cc = s_lat1[base + 28], d = s_lat1[base + 29];
                    int la = a & 31, lb = b2 & 31, lc = cc & 31, ld = d & 31;
                    int lm = min(min(la, lb), min(lc, ld));
                    bit = (int)(((a >> 7) & (unsigned)(la == lm)) | ((b2 >> 7) & (unsigned)(lb == lm)) |
                                ((cc >> 7) & (unsigned)(lc == lm)) | ((d >> 7) & (unsigned)(ld == lm)));
                }
                unsigned m = __ballot_sync(0xffffffffu, bit);
                if (bit) s_b1[py * 448 + n + __popc(m & ((1u << lane) - 1u))] =
                             (unsigned short)((ci << 4) | lane);
                n += __popc(m);
            }
            if (lane == 0) s_b1n[py] = n;
        }
        __syncthreads();

        // ---- P6: conv2 sparse scatter into own padded row (width 18) ----
        bool touched2 = false;
        {
            float* row = s_big + t * 18;
            const float* wb0 = w2 + o2 * 32 * 25;
            #pragma unroll
            for (int dy = -2; dy <= 2; dy++) {
                int y = rr2 + dy;
                if ((unsigned)y >= 14u) continue;
                int nb = s_b1n[y];
                if (!nb) continue;
                touched2 = true;
                const float* wb = wb0 + (dy + 2) * 5;
                int pc = -1; float wa=0.f, wbv=0.f, wc=0.f, wd=0.f, we=0.f;
                const unsigned short* bk = s_b1 + y * 448;
                for (int q = 0; q < nb; q++) {
                    int e = bk[q];
                    int ci = e >> 4, x = e & 15;
                    if (ci != pc) {
                        const float* wr = wb + ci * 25;
                        wa = wr[0]; wbv = wr[1]; wc = wr[2]; wd = wr[3]; we = wr[4];
                        pc = ci;
                    }
                    float* rp = row + x;
                    rp[4] += wa; rp[3] += wbv; rp[2] += wc; rp[1] += wd; rp[0] += we;
                }
            }
        }
        // ---- P7: L2 neuron update (own row) ----
        {
            unsigned char rf = s_rf2[t];
            int idx = t * 14;
            if (rf & 2) {
                for (int c = 0; c < 14; c++) s_lat2[idx + c] &= 0x7F;
            } else if ((rf & 1) || touched2) {
                bool wasActive = rf & 1;
                float* row = s_big + t * 18;
                bool alldead = true;
                int gbase = b * 12544 + idx;
                for (int ch = 0; ch < 14; ch += 2) {
                    float2 um2v, us2v;
                    if (wasActive) {
                        um2v = *(const float2*)(g_um2 + gbase + ch);
                        us2v = *(const float2*)(g_us2 + gbase + ch);
                    } else { um2v = make_float2(0.f, 0.f); us2v = um2v; }
                    float* um = &um2v.x; float* us = &us2v.x;
                    #pragma unroll
                    for (int j = 0; j < 2; j++) {
                        int c = ch + j;
                        float acc = row[c + 2];
                        float umv = um[j] * DMC + acc;
                        float usv = us[j] * DSC + acc;
                        um[j] = umv; us[j] = usv;
                        unsigned char tb = s_te2[idx + c];
                        unsigned char lb = s_lat2[idx + c];
                        bool sav = !(lb & 0x40);
                        float u = sav ? (umv - usv) : 0.f;
                        int spk = (u - 1.f > 0.f) ? 1 : 0;
                        if (tb > 0 || umv != 0.f) tb++;
                        unsigned char nlb = spk ? (unsigned char)((tb + 1) | 0xC0)
                                               : (unsigned char)(lb & 0x5F);
                        s_te2[idx + c] = tb; s_lat2[idx + c] = nlb;
                        alldead = alldead && ((nlb & 0x40) != 0);
                        c2 += spk;
                    }
                    *(float2*)(g_um2 + gbase + ch) = um2v;
                    *(float2*)(g_us2 + gbase + ch) = us2v;
                }
                rf |= 1; if (alldead) rf |= 2;
                s_rf2[t] = rf;
            }
        }
        __syncthreads();

        // ---- P8: pool2 -> 98-word bitmask ----
        if (w < 14) {
            #pragma unroll
            for (int k = 0; k < 7; k++) {
                int g = w * 7 + k;
                int L = g * 32 + lane;
                int ci = L / 49, p = L % 49, py = p / 7, px = p % 7;
                int base = ci * 196 + 2 * py * 14 + 2 * px;
                unsigned a = s_lat2[base],      b2 = s_lat2[base + 1];
                unsigned cc = s_lat2[base + 14], d = s_lat2[base + 15];
                int la = a & 31, lb = b2 & 31, lc = cc & 31, ld = d & 31;
                int lm = min(min(la, lb), min(lc, ld));
                int bit = (int)(((a >> 7) & (unsigned)(la == lm)) | ((b2 >> 7) & (unsigned)(lb == lm)) |
                                ((cc >> 7) & (unsigned)(lc == lm)) | ((d >> 7) & (unsigned)(ld == lm)));
                unsigned m = __ballot_sync(0xffffffffu, bit);
                if (lane == 0) s_pm[g] = m;
            }
        }
        __syncthreads();

        // ---- P9: fc1 (sparse gather over bitmask, ascending order) ----
        if (t < 600) {
            float acc = 0.f;
            for (int g = 0; g < 98; g++) {
                unsigned m = s_pm[g];
                while (m) {
                    int i = g * 32 + (__ffs(m) - 1);
                    m &= m - 1;
                    acc += g_wt1[i * 600 + t];
                }
            }
            float um = s_umf1[t] * DMC + acc;
            float us = s_usf1[t] * DSC + acc;
            s_umf1[t] = um; s_usf1[t] = us;
            int sav = s_savf1[t];
            float u = sav ? (um - us) : 0.f;
            int spk = (u - 1.f > 0.f) ? 1 : 0;
            if (spk) { s_savf1[t] = 0; c3++; }
            s_f1s[t] = (unsigned char)spk;
        }
        __syncthreads();

        // ---- P10: fc2 + output neuron ----
        if (w < 10) {
            float acc = 0.f;
            for (int i = lane; i < 600; i += 32)
                if (s_f1s[i]) acc += wf2[w * 600 + i];
            #pragma unroll
            for (int off = 16; off; off >>= 1)
                acc += __shfl_xor_sync(0xffffffffu, acc, off);
            if (lane == 0) {
                float um = s_umf2[w] * DMC + acc;
                float us = s_usf2[w] * DSC + acc;
                s_umf2[w] = um; s_usf2[w] = us;
                int sav = s_savf2[w];
                float u = sav ? (um - us) : 0.f;
                int spk = (u - 1.f > 0.f) ? 1 : 0;
                if (spk) s_savf2[w] = 0;
                float tel = s_tel[w];
                float uflag = (u != 0.f) ? 1.f : 0.f;
                if (tel + uflag != 0.f) tel += 1.f;
                s_tel[w] = tel;
                if (spk) { s_outt[w] += (tel - 16.f); s_outu[w] += u; c4++; }
            }
        }
        __syncthreads();
    }

    // ---- finalize: counts + outputs ----
    if (c0) atomicAdd(&s_cnt[0], c0);
    if (c1) atomicAdd(&s_cnt[1], c1);
    if (c2) atomicAdd(&s_cnt[2], c2);
    if (c3) atomicAdd(&s_cnt[3], c3);
    if (c4) atomicAdd(&s_cnt[4], c4);
    __syncthreads();
    if (t < 10) {
        out[b * 10 + t] = s_outt[t];
        out[1280 + b * 10 + t] = s_outu[t];
    }
    if (t < 5) g_bc[b * 8 + t] = (unsigned long long)s_cnt[t];
}

__global__ void k_pack(float* __restrict__ out) {
    int t = threadIdx.x;
    if (t < 5) {
        unsigned long long sum = 0;
        for (int b = 0; b < BATCH; b++) sum += g_bc[b * 8 + t];
        out[2560 + t] = (float)sum;
    }
}

// ------------------------------ launch --------------------------------------
extern "C" void kernel_launch(void* const* d_in, const int* in_sizes, int n_in,
                              void* d_out, int out_size) {
    const float *input = 0, *w1 = 0, *w2 = 0, *wf1 = 0, *wf2 = 0;
    for (int i = 0; i < n_in; i++) {
        long s = in_sizes[i];
        if (s == 100352 || s == 401408)        input = (const float*)d_in[i];
        else if (s == 800 || s == 3200)        w1    = (const float*)d_in[i];
        else if (s == 51200 || s == 204800)    w2    = (const float*)d_in[i];
        else if (s == 1881600 || s == 7526400) wf1   = (const float*)d_in[i];
        else if (s == 6000 || s == 24000)      wf2   = (const float*)d_in[i];
    }
    if (!input || !w1 || !w2 || !wf1 || !wf2) {
        const float* p[5] = {0, 0, 0, 0, 0};
        int k = 0;
        for (int i = 0; i < n_in && k < 5; i++)
            if (in_sizes[i] > 8) p[k++] = (const float*)d_in[i];
        if (k < 5)
            for (int i = 0; i < n_in && k < 5; i++) p[k++] = (const float*)d_in[i];
        input = p[0]; w1 = p[1]; w2 = p[2]; wf1 = p[3]; wf2 = p[4];
    }
    float* out = (float*)d_out;

    cudaFuncSetAttribute(k_fused, cudaFuncAttributeMaxDynamicSharedMemorySize,
                         SMEM_TOTAL);

    k_transpose<<<512, 256>>>(wf1);
    k_fused<<<BATCH, NT, SMEM_TOTAL>>>(input, w1, w2, wf2, out);
    k_pack<<<1, 32>>>(out);
}